// round 5
// baseline (speedup 1.0000x reference)
#include <cuda_runtime.h>
#include <cstdint>

#define C_ 128
#define F_ 1024
#define BK 8
#define NCHUNK (F_/BK)               // 128
#define NTHREADS 128
#define PITCH 12                     // banks (12g+tig)%32 all distinct -> conflict-free frags
#define A_FLOATS (128*PITCH)         // 1536
#define B_FLOATS (64*PITCH)          // 768
#define SMEM_BYTES ((2*A_FLOATS + 2*B_FLOATS)*4)   // 18432 B -> 4 CTAs/SM

__device__ __forceinline__ uint32_t tf32r(float v) {
    uint32_t r;
    asm("cvt.rna.tf32.f32 %0, %1;" : "=r"(r) : "f"(v));
    return r;
}

__device__ __forceinline__ void mma_tf32(float d[4], const uint32_t a[4], const uint32_t b[2]) {
    asm volatile(
        "mma.sync.aligned.m16n8k8.row.col.f32.tf32.tf32.f32 "
        "{%0,%1,%2,%3}, {%4,%5,%6,%7}, {%8,%9}, {%0,%1,%2,%3};"
        : "+f"(d[0]), "+f"(d[1]), "+f"(d[2]), "+f"(d[3])
        : "r"(a[0]), "r"(a[1]), "r"(a[2]), "r"(a[3]), "r"(b[0]), "r"(b[1]));
}

__device__ __forceinline__ void sts4(float* p, float4 v) {
    uint32_t x0 = tf32r(v.x), x1 = tf32r(v.y), x2 = tf32r(v.z), x3 = tf32r(v.w);
    *reinterpret_cast<uint4*>(p) = make_uint4(x0, x1, x2, x3);
}

__global__ void __launch_bounds__(NTHREADS, 4) cwlinear_mma_kernel(
    const float* __restrict__ x, const float* __restrict__ W,
    const float* __restrict__ bias, float* __restrict__ out)
{
    extern __shared__ float sm[];
    const int tid = threadIdx.x;
    const int wid = tid >> 5, lid = tid & 31;
    const int wm = wid >> 1, wn = wid & 1;          // warp grid 2(m) x 2(n), warp tile 64x32
    const int g = lid >> 2, tig = lid & 3;          // quad layout
    const int gt = blockIdx.x;                      // 0..7 g-tile
    const int c  = blockIdx.y;                      // 0..127 channel
    const int g0 = gt * 128;

    // ---- staging maps: A = 128 rows x 8 k (2 f4/thread), B = 64 x 8 (1 f4/thread)
    const float* Wg = W + ((size_t)c * F_ + g0) * F_;
    const float* a_g[2]; int a_so[2];
#pragma unroll
    for (int i = 0; i < 2; i++) {
        int f4 = tid + i * NTHREADS;                // 0..255 : 128 rows x 2 float4
        int r = f4 >> 1, c4 = f4 & 1;
        a_so[i] = r * PITCH + c4 * 4;
        a_g[i]  = Wg + (size_t)r * F_ + c4 * 4;
    }
    const float* b_g; int b_so;
    {
        int r = tid >> 1, c4 = tid & 1;             // 64 rows x 2 float4
        b_so = r * PITCH + c4 * 4;
        b_g  = x + ((size_t)r * C_ + c) * F_ + c4 * 4;
    }

    float d[4][4][4];
#pragma unroll
    for (int mt = 0; mt < 4; mt++)
#pragma unroll
        for (int nt = 0; nt < 4; nt++)
#pragma unroll
            for (int j = 0; j < 4; j++) d[mt][nt][j] = 0.0f;

    // ---- prologue prefetch (chunk 0)
    float4 ra[2], rb;
    ra[0] = __ldcs((const float4*)a_g[0]);
    ra[1] = __ldcs((const float4*)a_g[1]);
    rb    = __ldg((const float4*)b_g);

    // fragment bases (float indices), constant across chunks
    const int afrag0 = (wm * 64 + g) * PITCH + tig;     // + mt*16*PITCH ; +8*PITCH ; +4
    const int bfrag0 = (wn * 32 + g) * PITCH + tig;     // + nt*8*PITCH ; +4

    for (int kc = 0; kc < NCHUNK; kc++) {
        const int buf = kc & 1;
        float* Ab = sm + buf * A_FLOATS;
        float* Bb = sm + 2 * A_FLOATS + buf * B_FLOATS;

        sts4(Ab + a_so[0], ra[0]);
        sts4(Ab + a_so[1], ra[1]);
        sts4(Bb + b_so, rb);
        __syncthreads();

        if (kc + 1 < NCHUNK) {
            const int off = (kc + 1) * BK;
            ra[0] = __ldcs((const float4*)(a_g[0] + off));
            ra[1] = __ldcs((const float4*)(a_g[1] + off));
            rb    = __ldg((const float4*)(b_g + off));
        }

        uint32_t af[4][4];
#pragma unroll
        for (int mt = 0; mt < 4; mt++) {
            const float* ap = Ab + afrag0 + mt * 16 * PITCH;
            af[mt][0] = __float_as_uint(ap[0]);
            af[mt][1] = __float_as_uint(ap[8 * PITCH]);
            af[mt][2] = __float_as_uint(ap[4]);
            af[mt][3] = __float_as_uint(ap[8 * PITCH + 4]);
        }
        uint32_t bf[4][2];
#pragma unroll
        for (int nt = 0; nt < 4; nt++) {
            const float* bp = Bb + bfrag0 + nt * 8 * PITCH;
            bf[nt][0] = __float_as_uint(bp[0]);
            bf[nt][1] = __float_as_uint(bp[4]);
        }
#pragma unroll
        for (int mt = 0; mt < 4; mt++)
#pragma unroll
            for (int nt = 0; nt < 4; nt++)
                mma_tf32(d[mt][nt], af[mt], bf[nt]);
    }

    // ---- epilogue: y[b, c, g] = d + bias[c, g]
#pragma unroll
    for (int mt = 0; mt < 4; mt++) {
        const int m0 = g0 + wm * 64 + mt * 16 + g;          // g row (rows m0, m0+8)
        const float bv0 = bias[c * F_ + m0];
        const float bv1 = bias[c * F_ + m0 + 8];
#pragma unroll
        for (int nt = 0; nt < 4; nt++) {
            const int n0 = wn * 32 + nt * 8 + 2 * tig;      // batch col
            float* o0 = out + ((size_t)n0 * C_ + c) * F_;
            float* o1 = o0 + (size_t)C_ * F_;               // batch n0+1
            o0[m0]     = d[mt][nt][0] + bv0;
            o1[m0]     = d[mt][nt][1] + bv0;
            o0[m0 + 8] = d[mt][nt][2] + bv1;
            o1[m0 + 8] = d[mt][nt][3] + bv1;
        }
    }
}

extern "C" void kernel_launch(void* const* d_in, const int* in_sizes, int n_in,
                              void* d_out, int out_size) {
    const float* x    = (const float*)d_in[0];
    const float* W    = (const float*)d_in[1];
    const float* bias = (const float*)d_in[2];
    float* out = (float*)d_out;

    cudaFuncSetAttribute(cwlinear_mma_kernel,
                         cudaFuncAttributeMaxDynamicSharedMemorySize, SMEM_BYTES);
    cwlinear_mma_kernel<<<dim3(8, C_), NTHREADS, SMEM_BYTES>>>(x, W, bias, out);
}